// round 6
// baseline (speedup 1.0000x reference)
#include <cuda_runtime.h>
#include <cuda_bf16.h>
#include <cstdint>

// time_embeddings: out[b, i] = sin/cos(time[b] * 10000^(-(i//2)/640))
// B = 65536, DIM = 1280, fp32 out. HBM-write-bound (~335.5 MB out).
//
// Round-6: same TMA bulk-store design as round-5 (round-5 bench died at the
// container level with no harness output -> likely infra; theory untested).
// Each block computes a ROW PAIR (2 x 1280 fp32 = 10240 contiguous bytes)
// into double-buffered SMEM; thread 0 issues one cp.async.bulk
// shared->global per pair. Bypasses the per-thread L1TEX store path
// (round-4 evidence: L1TEX 73% = top unit, store instr count irrelevant).
// Hardened exit: block-wide sync, then drain wait_group 0 before return.

#define DIM      1280
#define C8S      (DIM / 8)         // 160 float8 chunks per row
#define BLOCK    320               // 2 rows x 160 chunks
#define GRID     3552              // multi-wave slack (round-3 lesson)
#define STAGES   2
#define PAIR_F   (2 * DIM)         // 2560 floats per row pair
#define PAIR_B   (PAIR_F * 4)      // 10240 bytes

__global__ __launch_bounds__(BLOCK, 6)
void time_emb_kernel(const float* __restrict__ time, float* __restrict__ out, int B)
{
    __shared__ __align__(128) float buf[STAGES][PAIR_F];   // 20 KB

    const int tid = threadIdx.x;
    const int sub = tid / C8S;              // 0/1: row within the pair
    const int c8  = tid - sub * C8S;        // 0..159: float8 chunk

    // rate(p) = 10000^(-p/640) = exp2(-log2(10000)/640 * p), p = i//2
    const float C = -13.287712379549449f / 640.0f;
    const int pb = 4 * c8;
    const float r0 = exp2f(C * (float)(pb + 0));
    const float r1 = exp2f(C * (float)(pb + 1));
    const float r2 = exp2f(C * (float)(pb + 2));
    const float r3 = exp2f(C * (float)(pb + 3));

    // Cody-Waite: 2*pi = HI + LO, HI=6.28125 exact for k<=160 (angle<=1000)
    const float INV2PI = 0.15915494309189535f;
    const float HI     = 6.28125f;
    const float LO     = 1.9353071795864769e-3f;

    const int npairs = B >> 1;              // B even (65536)
    int it = 0;

    for (int pair = blockIdx.x; pair < npairs; pair += GRID, ++it) {
        const int stage = it & 1;

        const float t = __ldg(&time[2 * pair + sub]);

        float a0 = t * r0, a1 = t * r1, a2 = t * r2, a3 = t * r3;

        float k0 = rintf(a0 * INV2PI), k1 = rintf(a1 * INV2PI);
        float k2 = rintf(a2 * INV2PI), k3 = rintf(a3 * INV2PI);

        float x0 = fmaf(k0, -LO, fmaf(k0, -HI, a0));
        float x1 = fmaf(k1, -LO, fmaf(k1, -HI, a1));
        float x2 = fmaf(k2, -LO, fmaf(k2, -HI, a2));
        float x3 = fmaf(k3, -LO, fmaf(k3, -HI, a3));

        float s0, c0, s1, c1, s2, c2, s3, c3;
        __sincosf(x0, &s0, &c0);
        __sincosf(x1, &s1, &c1);
        __sincosf(x2, &s2, &c2);
        __sincosf(x3, &s3, &c3);

        // Before overwriting this stage, ensure its previous TMA store has
        // finished READING the smem source (keep <=1 unread group pending).
        if (it >= STAGES) {
            if (tid == 0)
                asm volatile("cp.async.bulk.wait_group.read 1;" ::: "memory");
            __syncthreads();
        }

        // Write 8 floats (even col -> sin, odd -> cos) into the smem row pair.
        float4* p4 = reinterpret_cast<float4*>(&buf[stage][sub * DIM + 8 * c8]);
        p4[0] = make_float4(s0, c0, s1, c1);
        p4[1] = make_float4(s2, c2, s3, c3);
        __syncthreads();

        if (tid == 0) {
            asm volatile("fence.proxy.async.shared::cta;" ::: "memory");
            uint32_t saddr = (uint32_t)__cvta_generic_to_shared(&buf[stage][0]);
            float* gdst = out + (size_t)pair * PAIR_F;
            asm volatile(
                "cp.async.bulk.global.shared::cta.bulk_group [%0], [%1], %2;"
                :: "l"(gdst), "r"(saddr), "r"((int)PAIR_B)
                : "memory");
            asm volatile("cp.async.bulk.commit_group;" ::: "memory");
        }
    }

    // Hardened drain: all threads rendezvous, tid 0 waits until every
    // outstanding bulk store fully completed, then the block exits together.
    __syncthreads();
    if (tid == 0)
        asm volatile("cp.async.bulk.wait_group 0;" ::: "memory");
    __syncthreads();
}

extern "C" void kernel_launch(void* const* d_in, const int* in_sizes, int n_in,
                              void* d_out, int out_size)
{
    const float* time = (const float*)d_in[0];
    float* out = (float*)d_out;
    const int B = in_sizes[0];

    time_emb_kernel<<<GRID, BLOCK>>>(time, out, B);
}

// round 7
// speedup vs baseline: 1.0569x; 1.0569x over previous
#include <cuda_runtime.h>
#include <cuda_bf16.h>
#include <cstdint>

// time_embeddings: out[b, i] = sin/cos(time[b] * 10000^(-(i//2)/640))
// B = 65536, DIM = 1280, fp32 out. HBM-write-bound (~335.5 MB out,
// already at ~6.3 TB/s effective = ~80% of spec).
//
// Round-7: TMA store path disproven (round 6: slower). Revert to the best
// data path = round-4 direct st.global.cs.v8.f32 (no smem, no barriers,
// 32 regs), with ONE change: GRID 3552 -> 7104 (8 scheduling waves,
// ~4-5 iterations/block) to shrink the straggler tail that separates the
// timed back-to-back-replay number (53.4) from the profiled one (50.3).

#define DIM      1280
#define C8S      (DIM / 8)     // 160 float8 chunks per row
#define BLOCK    320           // 2 rows x 160 chunks per block-iteration
#define GRID     7104          // 148 SMs * 6 resident * 8 waves

__global__ __launch_bounds__(BLOCK, 6)
void time_emb_kernel(const float* __restrict__ time, float* __restrict__ out, int B)
{
    const int tid = threadIdx.x;
    const int sub = tid / C8S;              // 0/1: which row of the pair
    const int c8  = tid - sub * C8S;        // 0..159: float8 chunk in the row

    // rate(p) = 10000^(-p/640) = exp2(-log2(10000)/640 * p), p = i//2
    const float C = -13.287712379549449f / 640.0f;
    const int pb = 4 * c8;                  // first pair index of this chunk
    const float r0 = exp2f(C * (float)(pb + 0));
    const float r1 = exp2f(C * (float)(pb + 1));
    const float r2 = exp2f(C * (float)(pb + 2));
    const float r3 = exp2f(C * (float)(pb + 3));

    // Cody-Waite: 2*pi = HI + LO, HI=6.28125 exact for k<=160 (angle<=1000)
    const float INV2PI = 0.15915494309189535f;
    const float HI     = 6.28125f;
    const float LO     = 1.9353071795864769e-3f;

    const int stride = 2 * GRID;            // rows consumed per grid pass
    for (int row = 2 * blockIdx.x + sub; row < B; row += stride) {
        const float t = __ldg(&time[row]);

        float a0 = t * r0, a1 = t * r1, a2 = t * r2, a3 = t * r3;

        float k0 = rintf(a0 * INV2PI), k1 = rintf(a1 * INV2PI);
        float k2 = rintf(a2 * INV2PI), k3 = rintf(a3 * INV2PI);

        float x0 = fmaf(k0, -LO, fmaf(k0, -HI, a0));
        float x1 = fmaf(k1, -LO, fmaf(k1, -HI, a1));
        float x2 = fmaf(k2, -LO, fmaf(k2, -HI, a2));
        float x3 = fmaf(k3, -LO, fmaf(k3, -HI, a3));

        float s0, c0, s1, c1, s2, c2, s3, c3;
        __sincosf(x0, &s0, &c0);
        __sincosf(x1, &s1, &c1);
        __sincosf(x2, &s2, &c2);
        __sincosf(x3, &s3, &c3);

        // even col -> sin, odd col -> cos; cols 8*c8 .. 8*c8+7 of this row
        float* p = out + (size_t)row * DIM + 8 * c8;
        asm volatile(
            "st.global.cs.v8.f32 [%0], {%1, %2, %3, %4, %5, %6, %7, %8};"
            :: "l"(p),
               "f"(s0), "f"(c0), "f"(s1), "f"(c1),
               "f"(s2), "f"(c2), "f"(s3), "f"(c3)
            : "memory");
    }
}

extern "C" void kernel_launch(void* const* d_in, const int* in_sizes, int n_in,
                              void* d_out, int out_size)
{
    const float* time = (const float*)d_in[0];
    float* out = (float*)d_out;
    const int B = in_sizes[0];

    time_emb_kernel<<<GRID, BLOCK>>>(time, out, B);
}